// round 16
// baseline (speedup 1.0000x reference)
#include <cuda_runtime.h>
#include <math.h>
#include <stdint.h>

#define H 2048
#define NH 16
#define HD 128
#define SEQ 2048
#define BATCH 2
#define NQKV (H + 2*HD)   // 2304
#define SCALE 0.08838834764831843f  // 1/sqrt(128)
#define MROWS (BATCH*SEQ)

// ---------------- global scratch (allocation-free rule) ----------------
__device__ float    g_qkv[(size_t)MROWS * NQKV];   // tf32-rounded qkv
__device__ float    g_attn[(size_t)MROWS * H];     // tf32-rounded attn out
__device__ uint32_t g_xt[(size_t)MROWS * H];       // x, tf32-rounded
__device__ uint32_t g_wqt[(size_t)NQKV * H];       // Wqkv^T [N][K] rounded
__device__ uint32_t g_wpt[(size_t)H * H];          // Wproj^T [N][K] rounded

// ---------------- helpers ----------------
__device__ __forceinline__ uint32_t f2tf32(float x) {
    uint32_t r;
    asm("cvt.rna.tf32.f32 %0, %1;" : "=r"(r) : "f"(x));
    return r;
}
__device__ __forceinline__ void mma8(float* c, uint32_t a0, uint32_t a1,
                                     uint32_t a2, uint32_t a3,
                                     uint32_t b0, uint32_t b1) {
    asm volatile(
        "mma.sync.aligned.m16n8k8.row.col.f32.tf32.tf32.f32 "
        "{%0,%1,%2,%3}, {%4,%5,%6,%7}, {%8,%9}, {%0,%1,%2,%3};"
        : "+f"(c[0]), "+f"(c[1]), "+f"(c[2]), "+f"(c[3])
        : "r"(a0), "r"(a1), "r"(a2), "r"(a3), "r"(b0), "r"(b1));
}
__device__ __forceinline__ void ldsm4(uint32_t* r, uint32_t addr) {
    asm volatile("ldmatrix.sync.aligned.m8n8.x4.shared.b16 {%0,%1,%2,%3}, [%4];"
        : "=r"(r[0]), "=r"(r[1]), "=r"(r[2]), "=r"(r[3]) : "r"(addr));
}
__device__ __forceinline__ uint32_t sm_addr(const void* p) {
    return (uint32_t)__cvta_generic_to_shared(p);
}
__device__ __forceinline__ void cp16(uint32_t dst, const void* src) {
    asm volatile("cp.async.cg.shared.global [%0], [%1], 16;" :: "r"(dst), "l"(src));
}
__device__ __forceinline__ void cp_commit() {
    asm volatile("cp.async.commit_group;");
}
template<int N>
__device__ __forceinline__ void cp_wait() {
    asm volatile("cp.async.wait_group %0;" :: "n"(N));
}
__device__ __forceinline__ void bar64(int id) {
    asm volatile("bar.sync %0, 64;" :: "r"(id) : "memory");
}
__device__ __forceinline__ float fast_exp(float x) {
    float t = fmaxf(x * 1.4426950408889634f, -126.0f);
    float fl = floorf(t);
    float f = t - fl;
    float p =              1.535336188319500e-4f;
    p = fmaf(p, f, 1.339887440266574e-3f);
    p = fmaf(p, f, 9.618437357674640e-3f);
    p = fmaf(p, f, 5.550332471162809e-2f);
    p = fmaf(p, f, 2.402264791363012e-1f);
    p = fmaf(p, f, 6.931472028550421e-1f);
    p = fmaf(p, f, 1.0f);
    uint32_t sc = ((uint32_t)(int)(fl + 127.0f)) << 23;
    return p * __uint_as_float(sc);
}

// ---------------------------------------------------------------------------
// Pre-pass kernels
// ---------------------------------------------------------------------------
__global__ void __launch_bounds__(256) round_tf32(
    const float* __restrict__ in, uint32_t* __restrict__ out, int n4)
{
    int i = blockIdx.x * 256 + threadIdx.x;
    if (i >= n4) return;
    float4 v = ((const float4*)in)[i];
    uint4 t = {f2tf32(v.x), f2tf32(v.y), f2tf32(v.z), f2tf32(v.w)};
    ((uint4*)out)[i] = t;
}

__global__ void __launch_bounds__(256) transpose_round(
    const float* __restrict__ W, uint32_t* __restrict__ Wt, int K, int N)
{
    __shared__ float t[32][33];
    const int k0 = blockIdx.y * 32, n0 = blockIdx.x * 32;
    const int r = threadIdx.x >> 3, c4 = (threadIdx.x & 7) * 4;
    float4 v = *(const float4*)(W + (size_t)(k0 + r) * N + n0 + c4);
    t[r][c4] = v.x; t[r][c4+1] = v.y; t[r][c4+2] = v.z; t[r][c4+3] = v.w;
    __syncthreads();
    uint4 o = {f2tf32(t[c4][r]), f2tf32(t[c4+1][r]),
               f2tf32(t[c4+2][r]), f2tf32(t[c4+3][r])};
    *(uint4*)(Wt + (size_t)(n0 + r) * K + k0 + c4) = o;
}

// ---------------------------------------------------------------------------
// TF32 GEMM (round-12, unchanged): 256x128 tiles, 512 threads, 3-stage
// cp.async ring, one barrier per chunk, full-ldmatrix fragments.
// ---------------------------------------------------------------------------
#define GPQ 36
#define GSA (256 * GPQ)
#define GSB (128 * GPQ)
#define GST (GSA + GSB)
#define GEMM_SMEM_BYTES (3 * GST * 4)   // 165,888 B

template<bool ROUND_OUT>
__global__ void __launch_bounds__(512) gemm_tf32ca(
    const uint32_t* __restrict__ A, const uint32_t* __restrict__ Bt,
    const float* __restrict__ bias, float* __restrict__ C, int K, int N)
{
    extern __shared__ uint32_t sm[];
    const int tid  = threadIdx.x;
    const int warp = tid >> 5, lane = tid & 31;
    const int wm = warp >> 1, wn = warp & 1;
    const int g  = lane >> 2, tg = lane & 3;
    const int m0 = blockIdx.y * 256;
    const int n0 = blockIdx.x * 128;
    const uint32_t smb = sm_addr(sm);

    const int l15 = lane & 15;
    const int ahalfb = (lane >> 4) * 16;
    uint32_t aA[2];
    #pragma unroll
    for (int mt = 0; mt < 2; mt++)
        aA[mt] = smb + ((wm * 32 + mt * 16 + l15) * GPQ) * 4 + ahalfb;
    const int brow = (lane & 7) + ((lane >> 4) & 1) * 8;
    const int bcolb = ((lane >> 3) & 1) * 16;
    uint32_t bA[4];
    #pragma unroll
    for (int p = 0; p < 4; p++)
        bA[p] = smb + (GSA + (wn * 64 + p * 16 + brow) * GPQ) * 4 + bcolb;

    const int sr = tid >> 3, ss = (tid & 7) * 4;

    float acc[2][8][4];
    #pragma unroll
    for (int i = 0; i < 2; i++)
        #pragma unroll
        for (int j = 0; j < 8; j++)
            #pragma unroll
            for (int c = 0; c < 4; c++) acc[i][j][c] = 0.f;

    const int nkc = K / 32;
    #pragma unroll
    for (int s = 0; s < 2; s++) {
        const uint32_t off = s * GST * 4;
        #pragma unroll
        for (int i = 0; i < 4; i++) {
            const int row = sr + 64 * i;
            cp16(smb + off + (row * GPQ + ss) * 4,
                 A + (size_t)(m0 + row) * K + s * 32 + ss);
        }
        #pragma unroll
        for (int i = 0; i < 2; i++) {
            const int row = sr + 64 * i;
            cp16(smb + off + (GSA + row * GPQ + ss) * 4,
                 Bt + (size_t)(n0 + row) * K + s * 32 + ss);
        }
        cp_commit();
    }

    for (int kc = 0; kc < nkc; kc++) {
        const uint32_t soff = (uint32_t)(kc % 3) * GST * 4;
        if (kc + 1 < nkc) cp_wait<1>();
        else              cp_wait<0>();
        __syncthreads();

        if (kc + 2 < nkc) {
            const uint32_t noff = (uint32_t)((kc + 2) % 3) * GST * 4;
            #pragma unroll
            for (int i = 0; i < 4; i++) {
                const int row = sr + 64 * i;
                cp16(smb + noff + (row * GPQ + ss) * 4,
                     A + (size_t)(m0 + row) * K + (kc + 2) * 32 + ss);
            }
            #pragma unroll
            for (int i = 0; i < 2; i++) {
                const int row = sr + 64 * i;
                cp16(smb + noff + (GSA + row * GPQ + ss) * 4,
                     Bt + (size_t)(n0 + row) * K + (kc + 2) * 32 + ss);
            }
            cp_commit();
        }

        #pragma unroll
        for (int ks = 0; ks < 4; ks++) {
            uint32_t a[2][4], b[4][4];
            #pragma unroll
            for (int mt = 0; mt < 2; mt++)
                ldsm4(a[mt], aA[mt] + soff + ks * 32);
            #pragma unroll
            for (int p = 0; p < 4; p++)
                ldsm4(b[p], bA[p] + soff + ks * 32);
            #pragma unroll
            for (int mt = 0; mt < 2; mt++)
                #pragma unroll
                for (int nt = 0; nt < 8; nt++)
                    mma8(acc[mt][nt], a[mt][0], a[mt][1], a[mt][2], a[mt][3],
                         b[nt >> 1][(nt & 1) * 2], b[nt >> 1][(nt & 1) * 2 + 1]);
        }
    }

    #pragma unroll
    for (int nt = 0; nt < 8; nt++) {
        const int col = n0 + wn * 64 + nt * 8 + 2 * tg;
        float2 bv = *(const float2*)(bias + col);
        #pragma unroll
        for (int mt = 0; mt < 2; mt++) {
            const int row0 = m0 + wm * 32 + mt * 16 + g;
            float v0 = acc[mt][nt][0] + bv.x, v1 = acc[mt][nt][1] + bv.y;
            float v2 = acc[mt][nt][2] + bv.x, v3 = acc[mt][nt][3] + bv.y;
            if (ROUND_OUT) {
                v0 = __uint_as_float(f2tf32(v0));
                v1 = __uint_as_float(f2tf32(v1));
                v2 = __uint_as_float(f2tf32(v2));
                v3 = __uint_as_float(f2tf32(v3));
            }
            *(float2*)(C + (size_t)row0 * N + col)       = make_float2(v0, v1);
            *(float2*)(C + (size_t)(row0 + 8) * N + col) = make_float2(v2, v3);
        }
    }
}

// ---------------------------------------------------------------------------
// Causal MQA flash attention: BQ=128 x BK=64, 256 threads (warps 4x2),
// in-register pair softmax (round-15) + DOUBLE-BUFFERED V:
//  - V(kt+1) prefetch issued right after bar B into the other buffer,
//    overlapping PV(kt) and S(kt+1)
//  - post-PV barrier demoted full -> pair (bar.sync 64): Su/stats are
//    pair-private; V hazards removed by the double buffer
// Per tile: 2 full barriers + 2 pair barriers (was 3 full + 1 pair).
// ---------------------------------------------------------------------------
#define PQ 132
#define PV 136
#define PS 68
#define VSTG (64*PV)

#define OFF_Q 0
#define OFF_K (OFF_Q + 128*PQ)
#define OFF_V (OFF_K + 64*PQ)
#define OFF_S (OFF_V + 2*VSTG)
#define OFF_M (OFF_S + 128*PS)
#define OFF_PMX (OFF_M + 2*128)          // pair max partials [2][128]
#define OFF_PSM (OFF_PMX + 2*128)        // pair sum partials [2][128]
#define ATTN_U32 (OFF_PSM + 2*128)
#define ATTN_SMEM_BYTES (ATTN_U32 * 4)   // ~208.9 KB

__global__ void __launch_bounds__(256) mqa_attn_tf32(
    const float* __restrict__ qkv, float* __restrict__ out)
{
    extern __shared__ uint32_t smem_u[];
    uint32_t* Qs = smem_u + OFF_Q;
    uint32_t* Ks = smem_u + OFF_K;
    uint32_t* Vs = smem_u + OFF_V;            // 2 buffers of 64*PV
    uint32_t* Su = smem_u + OFF_S;            // P (tf32 bits)
    float* m_s  = (float*)(smem_u + OFF_M);
    float* l_s  = m_s + 128;
    float* pmxS = (float*)(smem_u + OFF_PMX);
    float* psmS = (float*)(smem_u + OFF_PSM);

    const int tid  = threadIdx.x;
    const int warp = tid >> 5, lane = tid & 31;
    const int g = lane >> 2, tg = lane & 3;
    const int wm = warp >> 1, wn = warp & 1;     // 4 x 2 warp grid
    const int qt = gridDim.x - 1 - blockIdx.x;   // heavy blocks first
    const int h = blockIdx.y, b = blockIdx.z;
    const int q0 = qt * 128;

    const float* qbase = qkv + (size_t)b * SEQ * NQKV + h * HD;
    const float* kbase = qkv + (size_t)b * SEQ * NQKV + H;
    const float* vbase = kbase + HD;

    const int l15 = lane & 15;
    const int ahalfb = (lane >> 4) * 16;
    const int brow  = (lane & 7) + ((lane >> 4) & 1) * 8;
    const int bcolb = ((lane >> 3) & 1) * 16;
    uint32_t qA[2], pA[2], kA[2];
    #pragma unroll
    for (int mt = 0; mt < 2; mt++) {
        const int row = wm * 32 + mt * 16 + l15;
        qA[mt] = sm_addr(Qs) + (row * PQ) * 4 + ahalfb;
        pA[mt] = sm_addr(Su) + (row * PS) * 4 + ahalfb;
    }
    #pragma unroll
    for (int p = 0; p < 2; p++)
        kA[p] = sm_addr(Ks) + ((wn * 32 + p * 16 + brow) * PQ) * 4 + bcolb;

    // prologue: Q (group 0), K0 (group 1), V0 -> buffer 0 (group 2)
    #pragma unroll
    for (int i = 0; i < 16; i++) {
        const int idx = tid + i * 256;
        const int r = idx >> 5, sg = (idx & 31) * 4;
        cp16(sm_addr(Qs) + (r * PQ + sg) * 4, qbase + (size_t)(q0 + r) * NQKV + sg);
    }
    cp_commit();
    #pragma unroll
    for (int i = 0; i < 8; i++) {
        const int idx = tid + i * 256;
        const int r = idx >> 5, sg = (idx & 31) * 4;
        cp16(sm_addr(Ks) + (r * PQ + sg) * 4, kbase + (size_t)r * NQKV + sg);
    }
    cp_commit();
    #pragma unroll
    for (int i = 0; i < 8; i++) {
        const int idx = tid + i * 256;
        const int r = idx >> 5, sg = (idx & 31) * 4;
        cp16(sm_addr(Vs) + (r * PV + sg) * 4, vbase + (size_t)r * NQKV + sg);
    }
    cp_commit();

    if (tid < 128) { m_s[tid] = -1e30f; l_s[tid] = 0.f; }

    float o[2][8][4];
    #pragma unroll
    for (int mt = 0; mt < 2; mt++)
        #pragma unroll
        for (int nt = 0; nt < 8; nt++)
            #pragma unroll
            for (int c = 0; c < 4; c++) o[mt][nt][c] = 0.f;

    const int nkt = 2 * qt + 2;
    for (int kt = 0; kt < nkt; kt++) {
        const int k0 = kt * 64;
        const uint32_t vbuf = (uint32_t)(kt & 1) * VSTG * 4;
        cp_wait<1>();        // bar A: K(kt) done (V(kt) may be in flight)
        __syncthreads();

        // ---- S = Q @ K^T (128x64), warp tile 32x32, 16 k8-steps ----
        float sacc[2][4][4];
        #pragma unroll
        for (int mt = 0; mt < 2; mt++)
            #pragma unroll
            for (int nt = 0; nt < 4; nt++)
                #pragma unroll
                for (int c = 0; c < 4; c++) sacc[mt][nt][c] = 0.f;

        #pragma unroll
        for (int ks = 0; ks < 16; ks++) {
            uint32_t a[2][4], b01[4], b23[4];
            ldsm4(a[0], qA[0] + ks * 32);
            ldsm4(a[1], qA[1] + ks * 32);
            ldsm4(b01, kA[0] + ks * 32);
            ldsm4(b23, kA[1] + ks * 32);
            #pragma unroll
            for (int mt = 0; mt < 2; mt++) {
                mma8(sacc[mt][0], a[mt][0], a[mt][1], a[mt][2], a[mt][3], b01[0], b01[1]);
                mma8(sacc[mt][1], a[mt][0], a[mt][1], a[mt][2], a[mt][3], b01[2], b01[3]);
                mma8(sacc[mt][2], a[mt][0], a[mt][1], a[mt][2], a[mt][3], b23[0], b23[1]);
                mma8(sacc[mt][3], a[mt][0], a[mt][1], a[mt][2], a[mt][3], b23[2], b23[3]);
            }
        }

        // ---- scale + mask + in-register row-max partials ----
        const bool need_mask = (k0 + 63 > q0 + wm * 32);
        float pmax[2][2];
        #pragma unroll
        for (int mt = 0; mt < 2; mt++) { pmax[mt][0] = -1e30f; pmax[mt][1] = -1e30f; }
        #pragma unroll
        for (int mt = 0; mt < 2; mt++) {
            const int mb = wm * 32 + mt * 16;
            #pragma unroll
            for (int nt = 0; nt < 4; nt++) {
                const int nb = wn * 32 + nt * 8;
                const int c0 = nb + 2 * tg, c1 = c0 + 1;
                const int r0 = mb + g, r1 = mb + g + 8;
                float s00 = sacc[mt][nt][0] * SCALE;
                float s01 = sacc[mt][nt][1] * SCALE;
                float s10 = sacc[mt][nt][2] * SCALE;
                float s11 = sacc[mt][nt][3] * SCALE;
                if (need_mask) {
                    if (k0 + c0 > q0 + r0) s00 = -1e30f;
                    if (k0 + c1 > q0 + r0) s01 = -1e30f;
                    if (k0 + c0 > q0 + r1) s10 = -1e30f;
                    if (k0 + c1 > q0 + r1) s11 = -1e30f;
                }
                sacc[mt][nt][0] = s00;  sacc[mt][nt][1] = s01;
                sacc[mt][nt][2] = s10;  sacc[mt][nt][3] = s11;
                pmax[mt][0] = fmaxf(pmax[mt][0], fmaxf(s00, s01));
                pmax[mt][1] = fmaxf(pmax[mt][1], fmaxf(s10, s11));
            }
        }
        #pragma unroll
        for (int mt = 0; mt < 2; mt++) {
            pmax[mt][0] = fmaxf(pmax[mt][0], __shfl_xor_sync(0xffffffffu, pmax[mt][0], 1));
            pmax[mt][0] = fmaxf(pmax[mt][0], __shfl_xor_sync(0xffffffffu, pmax[mt][0], 2));
            pmax[mt][1] = fmaxf(pmax[mt][1], __shfl_xor_sync(0xffffffffu, pmax[mt][1], 1));
            pmax[mt][1] = fmaxf(pmax[mt][1], __shfl_xor_sync(0xffffffffu, pmax[mt][1], 2));
        }
        if (tg == 0) {
            #pragma unroll
            for (int mt = 0; mt < 2; mt++) {
                const int r = wm * 32 + mt * 16 + g;
                pmxS[wn * 128 + r]     = pmax[mt][0];
                pmxS[wn * 128 + r + 8] = pmax[mt][1];
            }
        }
        bar64(wm + 1);   // pair barrier: max partials visible

        float mnew[2][2], fr[2][2];
        #pragma unroll
        for (int mt = 0; mt < 2; mt++) {
            const int r = wm * 32 + mt * 16 + g;
            float oth0 = pmxS[(1 - wn) * 128 + r];
            float oth1 = pmxS[(1 - wn) * 128 + r + 8];
            float mold0 = m_s[r], mold1 = m_s[r + 8];
            mnew[mt][0] = fmaxf(fmaxf(pmax[mt][0], oth0), mold0);
            mnew[mt][1] = fmaxf(fmaxf(pmax[mt][1], oth1), mold1);
            fr[mt][0] = fast_exp(mold0 - mnew[mt][0]);
            fr[mt][1] = fast_exp(mold1 - mnew[mt][1]);
        }

        // exp in registers; write P (tf32) once; partial sums
        float psum[2][2] = {{0.f, 0.f}, {0.f, 0.f}};
        #pragma unroll
        for (int mt = 0; mt < 2; mt++) {
            const int mb = wm * 32 + mt * 16;
            #pragma unroll
            for (int nt = 0; nt < 4; nt++) {
                const int nb = wn * 32 + nt * 8;
                const int c0 = nb + 2 * tg;
                const int r0 = mb + g, r1 = mb + g + 8;
                float p00 = fast_exp(sacc[mt][nt][0] - mnew[mt][0]);
                float p01 = fast_exp(sacc[mt][nt][1] - mnew[mt][0]);
                float p10 = fast_exp(sacc[mt][nt][2] - mnew[mt][1]);
                float p11 = fast_exp(sacc[mt][nt][3] - mnew[mt][1]);
                psum[mt][0] += p00 + p01;
                psum[mt][1] += p10 + p11;
                uint2 w0 = {f2tf32(p00), f2tf32(p01)};
                uint2 w1 = {f2tf32(p10), f2tf32(p11)};
                *(uint2*)&Su[r0 * PS + c0] = w0;
                *(uint2*)&Su[r1 * PS + c0] = w1;
            }
        }
        #pragma unroll
        for (int mt = 0; mt < 2; mt++) {
            psum[mt][0] += __shfl_xor_sync(0xffffffffu, psum[mt][0], 1);
            psum[mt][0] += __shfl_xor_sync(0xffffffffu, psum[mt][0], 2);
            psum[mt][1] += __shfl_xor_sync(0xffffffffu, psum[mt][1], 1);
            psum[mt][1] += __shfl_xor_sync(0xffffffffu, psum[mt][1], 2);
        }
        if (tg == 0) {
            #pragma unroll
            for (int mt = 0; mt < 2; mt++) {
                const int r = wm * 32 + mt * 16 + g;
                psmS[wn * 128 + r]     = psum[mt][0];
                psmS[wn * 128 + r + 8] = psum[mt][1];
            }
        }

        cp_wait<0>();        // V(kt) done
        __syncthreads();     // bar B: V ready + P & partial sums visible

        // prefetch K(kt+1) and V(kt+1) (other buffer) — overlap PV + next S
        if (kt + 1 < nkt) {
            const uint32_t vnext = (uint32_t)((kt + 1) & 1) * VSTG * 4;
            #pragma unroll
            for (int i = 0; i < 8; i++) {
                const int idx = tid + i * 256;
                const int r = idx >> 5, sg = (idx & 31) * 4;
                cp16(sm_addr(Ks) + (r * PQ + sg) * 4,
                     kbase + (size_t)(k0 + 64 + r) * NQKV + sg);
            }
            cp_commit();
            #pragma unroll
            for (int i = 0; i < 8; i++) {
                const int idx = tid + i * 256;
                const int r = idx >> 5, sg = (idx & 31) * 4;
                cp16(sm_addr(Vs) + vnext + (r * PV + sg) * 4,
                     vbase + (size_t)(k0 + 64 + r) * NQKV + sg);
            }
            cp_commit();
        }

        // running-stats update (one lane per row)
        if (wn == 0 && tg == 0) {
            #pragma unroll
            for (int mt = 0; mt < 2; mt++) {
                const int r = wm * 32 + mt * 16 + g;
                l_s[r]     = l_s[r]     * fr[mt][0] + psmS[r]     + psmS[128 + r];
                l_s[r + 8] = l_s[r + 8] * fr[mt][1] + psmS[r + 8] + psmS[128 + r + 8];
                m_s[r]     = mnew[mt][0];
                m_s[r + 8] = mnew[mt][1];
            }
        }

        // ---- O = O*f + P @ V (128x128), warp tile 32x64, 8 k8-steps ----
        #pragma unroll
        for (int mt = 0; mt < 2; mt++)
            #pragma unroll
            for (int nt = 0; nt < 8; nt++) {
                o[mt][nt][0] *= fr[mt][0];  o[mt][nt][1] *= fr[mt][0];
                o[mt][nt][2] *= fr[mt][1];  o[mt][nt][3] *= fr[mt][1];
            }

        const uint32_t* Vcur = (const uint32_t*)((const char*)Vs + vbuf);
        #pragma unroll
        for (int ks = 0; ks < 8; ks++) {
            const int kb = ks * 8;
            uint32_t a[2][4];
            ldsm4(a[0], pA[0] + ks * 32);
            ldsm4(a[1], pA[1] + ks * 32);
            #pragma unroll
            for (int nt = 0; nt < 8; nt++) {
                const int nb = wn * 64 + nt * 8;
                uint32_t b0 = Vcur[(kb + tg    )*PV + nb + g];
                uint32_t b1 = Vcur[(kb + tg + 4)*PV + nb + g];
                #pragma unroll
                for (int mt = 0; mt < 2; mt++)
                    mma8(o[mt][nt], a[mt][0], a[mt][1], a[mt][2], a[mt][3], b0, b1);
            }
        }
        bar64(wm + 1);   // pair barrier: Su/stat reuse protection only
    }

    __syncthreads();
    // final write: o / l, tf32-rounded for the proj GEMM's raw-bits path
    #pragma unroll
    for (int mt = 0; mt < 2; mt++) {
        const int mb = wm * 32 + mt * 16;
        const float inv0 = 1.f / l_s[mb + g];
        const float inv1 = 1.f / l_s[mb + g + 8];
        #pragma unroll
        for (int nt = 0; nt < 8; nt++) {
            const int col = wn * 64 + nt * 8 + 2 * tg;
            size_t row0 = (size_t)(b * SEQ + q0 + mb + g) * H + h * HD + col;
            size_t row1 = (size_t)(b * SEQ + q0 + mb + g + 8) * H + h * HD + col;
            float2 r0 = {__uint_as_float(f2tf32(o[mt][nt][0] * inv0)),
                         __uint_as_float(f2tf32(o[mt][nt][1] * inv0))};
            float2 r1 = {__uint_as_float(f2tf32(o[mt][nt][2] * inv1)),
                         __uint_as_float(f2tf32(o[mt][nt][3] * inv1))};
            *(float2*)(out + row0) = r0;
            *(float2*)(out + row1) = r1;
        }
    }
}

// ---------------------------------------------------------------------------

extern "C" void kernel_launch(void* const* d_in, const int* in_sizes, int n_in,
                              void* d_out, int out_size)
{
    (void)in_sizes; (void)n_in; (void)out_size;
    const float* x     = (const float*)d_in[0];
    const float* Wqkv  = (const float*)d_in[1];
    const float* bqkv  = (const float*)d_in[2];
    const float* Wproj = (const float*)d_in[3];
    const float* bproj = (const float*)d_in[4];
    float* out = (float*)d_out;

    float *qkv_p, *attn_p;
    uint32_t *xt, *wqt, *wpt;
    cudaGetSymbolAddress((void**)&qkv_p, g_qkv);
    cudaGetSymbolAddress((void**)&attn_p, g_attn);
    cudaGetSymbolAddress((void**)&xt, g_xt);
    cudaGetSymbolAddress((void**)&wqt, g_wqt);
    cudaGetSymbolAddress((void**)&wpt, g_wpt);

    cudaFuncSetAttribute(mqa_attn_tf32, cudaFuncAttributeMaxDynamicSharedMemorySize,
                         ATTN_SMEM_BYTES);
    cudaFuncSetAttribute(gemm_tf32ca<true>, cudaFuncAttributeMaxDynamicSharedMemorySize,
                         GEMM_SMEM_BYTES);
    cudaFuncSetAttribute(gemm_tf32ca<false>, cudaFuncAttributeMaxDynamicSharedMemorySize,
                         GEMM_SMEM_BYTES);

    // 0) pre-round + pre-transpose
    round_tf32<<<(MROWS * H / 4 + 255) / 256, 256>>>(x, xt, MROWS * H / 4);
    transpose_round<<<dim3(NQKV / 32, H / 32), 256>>>(Wqkv, wqt, H, NQKV);
    transpose_round<<<dim3(H / 32, H / 32), 256>>>(Wproj, wpt, H, H);

    // 1) QKV GEMM (256x128 tiles, 3-stage cp.async; output tf32-rounded)
    gemm_tf32ca<true><<<dim3(NQKV / 128, MROWS / 256), 512, GEMM_SMEM_BYTES>>>(
        xt, wqt, bqkv, qkv_p, H, NQKV);

    // 2) causal MQA flash attention (in-register softmax + double-buffered V)
    mqa_attn_tf32<<<dim3(SEQ / 128, NH, BATCH), 256, ATTN_SMEM_BYTES>>>(qkv_p, attn_p);

    // 3) proj GEMM -> d_out (fp32 output, no rounding)
    gemm_tf32ca<false><<<dim3(H / 128, MROWS / 256), 512, GEMM_SMEM_BYTES>>>(
        (const uint32_t*)attn_p, wpt, bproj, out, H, H);
}

// round 17
// speedup vs baseline: 1.0358x; 1.0358x over previous
#include <cuda_runtime.h>
#include <math.h>
#include <stdint.h>

#define H 2048
#define NH 16
#define HD 128
#define SEQ 2048
#define BATCH 2
#define NQKV (H + 2*HD)   // 2304
#define SCALE 0.08838834764831843f  // 1/sqrt(128)
#define MROWS (BATCH*SEQ)

// ---------------- global scratch (allocation-free rule) ----------------
__device__ float    g_qkv[(size_t)MROWS * NQKV];   // tf32-rounded qkv
__device__ float    g_attn[(size_t)MROWS * H];     // tf32-rounded attn out
__device__ uint32_t g_xt[(size_t)MROWS * H];       // x, tf32-rounded
__device__ uint32_t g_wqt[(size_t)NQKV * H];       // Wqkv^T [N][K] rounded
__device__ uint32_t g_wpt[(size_t)H * H];          // Wproj^T [N][K] rounded

// ---------------- helpers ----------------
__device__ __forceinline__ uint32_t f2tf32(float x) {
    uint32_t r;
    asm("cvt.rna.tf32.f32 %0, %1;" : "=r"(r) : "f"(x));
    return r;
}
__device__ __forceinline__ void mma8(float* c, uint32_t a0, uint32_t a1,
                                     uint32_t a2, uint32_t a3,
                                     uint32_t b0, uint32_t b1) {
    asm volatile(
        "mma.sync.aligned.m16n8k8.row.col.f32.tf32.tf32.f32 "
        "{%0,%1,%2,%3}, {%4,%5,%6,%7}, {%8,%9}, {%0,%1,%2,%3};"
        : "+f"(c[0]), "+f"(c[1]), "+f"(c[2]), "+f"(c[3])
        : "r"(a0), "r"(a1), "r"(a2), "r"(a3), "r"(b0), "r"(b1));
}
__device__ __forceinline__ void ldsm4(uint32_t* r, uint32_t addr) {
    asm volatile("ldmatrix.sync.aligned.m8n8.x4.shared.b16 {%0,%1,%2,%3}, [%4];"
        : "=r"(r[0]), "=r"(r[1]), "=r"(r[2]), "=r"(r[3]) : "r"(addr));
}
__device__ __forceinline__ uint32_t sm_addr(const void* p) {
    return (uint32_t)__cvta_generic_to_shared(p);
}
__device__ __forceinline__ void cp16(uint32_t dst, const void* src) {
    asm volatile("cp.async.cg.shared.global [%0], [%1], 16;" :: "r"(dst), "l"(src));
}
__device__ __forceinline__ void cp_commit() {
    asm volatile("cp.async.commit_group;");
}
template<int N>
__device__ __forceinline__ void cp_wait() {
    asm volatile("cp.async.wait_group %0;" :: "n"(N));
}
__device__ __forceinline__ void barn(int id, int n) {
    asm volatile("bar.sync %0, %1;" :: "r"(id), "r"(n) : "memory");
}
__device__ __forceinline__ float fast_exp(float x) {
    float t = fmaxf(x * 1.4426950408889634f, -126.0f);
    float fl = floorf(t);
    float f = t - fl;
    float p =              1.535336188319500e-4f;
    p = fmaf(p, f, 1.339887440266574e-3f);
    p = fmaf(p, f, 9.618437357674640e-3f);
    p = fmaf(p, f, 5.550332471162809e-2f);
    p = fmaf(p, f, 2.402264791363012e-1f);
    p = fmaf(p, f, 6.931472028550421e-1f);
    p = fmaf(p, f, 1.0f);
    uint32_t sc = ((uint32_t)(int)(fl + 127.0f)) << 23;
    return p * __uint_as_float(sc);
}

// ---------------------------------------------------------------------------
// Pre-pass kernels
// ---------------------------------------------------------------------------
__global__ void __launch_bounds__(256) round_tf32(
    const float* __restrict__ in, uint32_t* __restrict__ out, int n4)
{
    int i = blockIdx.x * 256 + threadIdx.x;
    if (i >= n4) return;
    float4 v = ((const float4*)in)[i];
    uint4 t = {f2tf32(v.x), f2tf32(v.y), f2tf32(v.z), f2tf32(v.w)};
    ((uint4*)out)[i] = t;
}

__global__ void __launch_bounds__(256) transpose_round(
    const float* __restrict__ W, uint32_t* __restrict__ Wt, int K, int N)
{
    __shared__ float t[32][33];
    const int k0 = blockIdx.y * 32, n0 = blockIdx.x * 32;
    const int r = threadIdx.x >> 3, c4 = (threadIdx.x & 7) * 4;
    float4 v = *(const float4*)(W + (size_t)(k0 + r) * N + n0 + c4);
    t[r][c4] = v.x; t[r][c4+1] = v.y; t[r][c4+2] = v.z; t[r][c4+3] = v.w;
    __syncthreads();
    uint4 o = {f2tf32(t[c4][r]), f2tf32(t[c4+1][r]),
               f2tf32(t[c4+2][r]), f2tf32(t[c4+3][r])};
    *(uint4*)(Wt + (size_t)(n0 + r) * K + k0 + c4) = o;
}

// ---------------------------------------------------------------------------
// TF32 GEMM (round-12, unchanged): 256x128 tiles, 512 threads, 3-stage
// cp.async ring, one barrier per chunk, full-ldmatrix fragments.
// ---------------------------------------------------------------------------
#define GPQ 36
#define GSA (256 * GPQ)
#define GSB (128 * GPQ)
#define GST (GSA + GSB)
#define GEMM_SMEM_BYTES (3 * GST * 4)   // 165,888 B

template<bool ROUND_OUT>
__global__ void __launch_bounds__(512) gemm_tf32ca(
    const uint32_t* __restrict__ A, const uint32_t* __restrict__ Bt,
    const float* __restrict__ bias, float* __restrict__ C, int K, int N)
{
    extern __shared__ uint32_t sm[];
    const int tid  = threadIdx.x;
    const int warp = tid >> 5, lane = tid & 31;
    const int wm = warp >> 1, wn = warp & 1;
    const int g  = lane >> 2, tg = lane & 3;
    const int m0 = blockIdx.y * 256;
    const int n0 = blockIdx.x * 128;
    const uint32_t smb = sm_addr(sm);

    const int l15 = lane & 15;
    const int ahalfb = (lane >> 4) * 16;
    uint32_t aA[2];
    #pragma unroll
    for (int mt = 0; mt < 2; mt++)
        aA[mt] = smb + ((wm * 32 + mt * 16 + l15) * GPQ) * 4 + ahalfb;
    const int brow = (lane & 7) + ((lane >> 4) & 1) * 8;
    const int bcolb = ((lane >> 3) & 1) * 16;
    uint32_t bA[4];
    #pragma unroll
    for (int p = 0; p < 4; p++)
        bA[p] = smb + (GSA + (wn * 64 + p * 16 + brow) * GPQ) * 4 + bcolb;

    const int sr = tid >> 3, ss = (tid & 7) * 4;

    float acc[2][8][4];
    #pragma unroll
    for (int i = 0; i < 2; i++)
        #pragma unroll
        for (int j = 0; j < 8; j++)
            #pragma unroll
            for (int c = 0; c < 4; c++) acc[i][j][c] = 0.f;

    const int nkc = K / 32;
    #pragma unroll
    for (int s = 0; s < 2; s++) {
        const uint32_t off = s * GST * 4;
        #pragma unroll
        for (int i = 0; i < 4; i++) {
            const int row = sr + 64 * i;
            cp16(smb + off + (row * GPQ + ss) * 4,
                 A + (size_t)(m0 + row) * K + s * 32 + ss);
        }
        #pragma unroll
        for (int i = 0; i < 2; i++) {
            const int row = sr + 64 * i;
            cp16(smb + off + (GSA + row * GPQ + ss) * 4,
                 Bt + (size_t)(n0 + row) * K + s * 32 + ss);
        }
        cp_commit();
    }

    for (int kc = 0; kc < nkc; kc++) {
        const uint32_t soff = (uint32_t)(kc % 3) * GST * 4;
        if (kc + 1 < nkc) cp_wait<1>();
        else              cp_wait<0>();
        __syncthreads();

        if (kc + 2 < nkc) {
            const uint32_t noff = (uint32_t)((kc + 2) % 3) * GST * 4;
            #pragma unroll
            for (int i = 0; i < 4; i++) {
                const int row = sr + 64 * i;
                cp16(smb + noff + (row * GPQ + ss) * 4,
                     A + (size_t)(m0 + row) * K + (kc + 2) * 32 + ss);
            }
            #pragma unroll
            for (int i = 0; i < 2; i++) {
                const int row = sr + 64 * i;
                cp16(smb + noff + (GSA + row * GPQ + ss) * 4,
                     Bt + (size_t)(n0 + row) * K + (kc + 2) * 32 + ss);
            }
            cp_commit();
        }

        #pragma unroll
        for (int ks = 0; ks < 4; ks++) {
            uint32_t a[2][4], b[4][4];
            #pragma unroll
            for (int mt = 0; mt < 2; mt++)
                ldsm4(a[mt], aA[mt] + soff + ks * 32);
            #pragma unroll
            for (int p = 0; p < 4; p++)
                ldsm4(b[p], bA[p] + soff + ks * 32);
            #pragma unroll
            for (int mt = 0; mt < 2; mt++)
                #pragma unroll
                for (int nt = 0; nt < 8; nt++)
                    mma8(acc[mt][nt], a[mt][0], a[mt][1], a[mt][2], a[mt][3],
                         b[nt >> 1][(nt & 1) * 2], b[nt >> 1][(nt & 1) * 2 + 1]);
        }
    }

    #pragma unroll
    for (int nt = 0; nt < 8; nt++) {
        const int col = n0 + wn * 64 + nt * 8 + 2 * tg;
        float2 bv = *(const float2*)(bias + col);
        #pragma unroll
        for (int mt = 0; mt < 2; mt++) {
            const int row0 = m0 + wm * 32 + mt * 16 + g;
            float v0 = acc[mt][nt][0] + bv.x, v1 = acc[mt][nt][1] + bv.y;
            float v2 = acc[mt][nt][2] + bv.x, v3 = acc[mt][nt][3] + bv.y;
            if (ROUND_OUT) {
                v0 = __uint_as_float(f2tf32(v0));
                v1 = __uint_as_float(f2tf32(v1));
                v2 = __uint_as_float(f2tf32(v2));
                v3 = __uint_as_float(f2tf32(v3));
            }
            *(float2*)(C + (size_t)row0 * N + col)       = make_float2(v0, v1);
            *(float2*)(C + (size_t)(row0 + 8) * N + col) = make_float2(v2, v3);
        }
    }
}

// ---------------------------------------------------------------------------
// Causal MQA flash attention, SPLIT-K halves:
// 512 threads = 2 independent halves of 8 warps. Half h processes k-tiles
// [h*(2qt+2), (h+1)*(2qt+2)) of 32 rows each with its OWN K/V smem, own
// running (m,l) and own O accumulators — synchronized only by half-scope
// named barriers, so the two halves' S/softmax/PV phases interleave and
// keep both the tensor and FMA pipes busy. Exact split-softmax merge at
// the end (half 1 passes O through the dead Q region).
// ---------------------------------------------------------------------------
#define PQ 132
#define PV 136
#define PS 36

#define AQ_U32   (128*PQ)                 // 16896
#define H_K      0
#define H_V      (32*PQ)                  // 4224
#define H_SU     (H_V + 32*PV)            // 8576
#define H_M      (H_SU + 128*PS)          // 13184 (m 128, l 128)
#define H_PMX    (H_M + 256)              // 13440
#define H_PSM    (H_PMX + 256)            // 13696
#define H_U32    (H_PSM + 256)            // 13952
#define ATTN_U32 (AQ_U32 + 2*H_U32)       // 44800
#define ATTN_SMEM_BYTES (ATTN_U32 * 4)    // 179,200 B

__global__ void __launch_bounds__(512) mqa_attn_tf32(
    const float* __restrict__ qkv, float* __restrict__ out)
{
    extern __shared__ uint32_t smem_u[];
    uint32_t* Qs = smem_u;

    const int tid  = threadIdx.x;
    const int warp = tid >> 5, lane = tid & 31;
    const int half = warp >> 3;                   // 0 or 1
    const int hwarp = warp & 7;
    const int wm = hwarp >> 1, wn = hwarp & 1;    // 4 x 2 grid per half
    const int g = lane >> 2, tg = lane & 3;
    const int tid_h = tid & 255;
    const int qt = gridDim.x - 1 - blockIdx.x;    // heavy blocks first
    const int hh = blockIdx.y, b = blockIdx.z;
    const int q0 = qt * 128;

    uint32_t* Hbase = smem_u + AQ_U32 + half * H_U32;
    uint32_t* Ks = Hbase + H_K;
    uint32_t* Vs = Hbase + H_V;
    uint32_t* Su = Hbase + H_SU;
    float* m_s  = (float*)(Hbase + H_M);
    float* l_s  = m_s + 128;
    float* pmxS = (float*)(Hbase + H_PMX);
    float* psmS = (float*)(Hbase + H_PSM);

    const float* qbase = qkv + (size_t)b * SEQ * NQKV + hh * HD;
    const float* kbase = qkv + (size_t)b * SEQ * NQKV + H;
    const float* vbase = kbase + HD;

    const int l15 = lane & 15;
    const int ahalfb = (lane >> 4) * 16;
    const int brow  = (lane & 7) + ((lane >> 4) & 1) * 8;
    const int bcolb = ((lane >> 3) & 1) * 16;
    uint32_t qA[2], pA[2];
    #pragma unroll
    for (int mt = 0; mt < 2; mt++) {
        const int row = wm * 32 + mt * 16 + l15;
        qA[mt] = sm_addr(Qs) + (row * PQ) * 4 + ahalfb;
        pA[mt] = sm_addr(Su) + (row * PS) * 4 + ahalfb;
    }
    const uint32_t kA = sm_addr(Ks) + ((wn * 16 + brow) * PQ) * 4 + bcolb;

    const int pairbar = 1 + wm + 4 * half;   // ids 1..8
    const int hbar = 9 + half;               // ids 9,10

    const int nh = 2 * qt + 2;               // 32-tiles per half
    const int t0 = half * nh;

    // prologue: Q by all 512 (group), then per-half K(t0), V(t0)
    #pragma unroll
    for (int i = 0; i < 8; i++) {
        const int idx = tid + i * 512;
        const int r = idx >> 5, sg = (idx & 31) * 4;
        cp16(sm_addr(Qs) + (r * PQ + sg) * 4, qbase + (size_t)(q0 + r) * NQKV + sg);
    }
    cp_commit();
    #pragma unroll
    for (int i = 0; i < 4; i++) {
        const int idx = tid_h + i * 256;
        const int r = idx >> 5, sg = (idx & 31) * 4;
        cp16(sm_addr(Ks) + (r * PQ + sg) * 4,
             kbase + (size_t)(t0 * 32 + r) * NQKV + sg);
    }
    cp_commit();
    #pragma unroll
    for (int i = 0; i < 4; i++) {
        const int idx = tid_h + i * 256;
        const int r = idx >> 5, sg = (idx & 31) * 4;
        cp16(sm_addr(Vs) + (r * PV + sg) * 4,
             vbase + (size_t)(t0 * 32 + r) * NQKV + sg);
    }
    cp_commit();

    if (tid_h < 128) { m_s[tid_h] = -1e30f; l_s[tid_h] = 0.f; }

    cp_wait<2>();        // Q landed (per-thread)
    __syncthreads();     // Q globally visible; halves now decouple

    float o[2][8][4];
    #pragma unroll
    for (int mt = 0; mt < 2; mt++)
        #pragma unroll
        for (int nt = 0; nt < 8; nt++)
            #pragma unroll
            for (int c = 0; c < 4; c++) o[mt][nt][c] = 0.f;

    for (int kl = 0; kl < nh; kl++) {
        const int k0 = (t0 + kl) * 32;
        cp_wait<1>();            // K(kl) done (V may be in flight)
        barn(hbar, 256);

        // ---- S = Q @ K^T (128x32), warp tile 32x16, 16 k8-steps ----
        float sacc[2][2][4];
        #pragma unroll
        for (int mt = 0; mt < 2; mt++)
            #pragma unroll
            for (int nt = 0; nt < 2; nt++)
                #pragma unroll
                for (int c = 0; c < 4; c++) sacc[mt][nt][c] = 0.f;

        #pragma unroll
        for (int ks = 0; ks < 16; ks++) {
            uint32_t a[2][4], bb[4];
            ldsm4(a[0], qA[0] + ks * 32);
            ldsm4(a[1], qA[1] + ks * 32);
            ldsm4(bb, kA + ks * 32);
            #pragma unroll
            for (int mt = 0; mt < 2; mt++) {
                mma8(sacc[mt][0], a[mt][0], a[mt][1], a[mt][2], a[mt][3], bb[0], bb[1]);
                mma8(sacc[mt][1], a[mt][0], a[mt][1], a[mt][2], a[mt][3], bb[2], bb[3]);
            }
        }

        // ---- scale + mask + in-register row-max partials ----
        const bool need_mask = (k0 + 31 > q0 + wm * 32);
        float pmax[2][2];
        #pragma unroll
        for (int mt = 0; mt < 2; mt++) { pmax[mt][0] = -1e30f; pmax[mt][1] = -1e30f; }
        #pragma unroll
        for (int mt = 0; mt < 2; mt++) {
            const int mb = wm * 32 + mt * 16;
            #pragma unroll
            for (int nt = 0; nt < 2; nt++) {
                const int nb = wn * 16 + nt * 8;
                const int c0 = nb + 2 * tg, c1 = c0 + 1;
                const int r0 = mb + g, r1 = mb + g + 8;
                float s00 = sacc[mt][nt][0] * SCALE;
                float s01 = sacc[mt][nt][1] * SCALE;
                float s10 = sacc[mt][nt][2] * SCALE;
                float s11 = sacc[mt][nt][3] * SCALE;
                if (need_mask) {
                    if (k0 + c0 > q0 + r0) s00 = -1e30f;
                    if (k0 + c1 > q0 + r0) s01 = -1e30f;
                    if (k0 + c0 > q0 + r1) s10 = -1e30f;
                    if (k0 + c1 > q0 + r1) s11 = -1e30f;
                }
                sacc[mt][nt][0] = s00;  sacc[mt][nt][1] = s01;
                sacc[mt][nt][2] = s10;  sacc[mt][nt][3] = s11;
                pmax[mt][0] = fmaxf(pmax[mt][0], fmaxf(s00, s01));
                pmax[mt][1] = fmaxf(pmax[mt][1], fmaxf(s10, s11));
            }
        }
        #pragma unroll
        for (int mt = 0; mt < 2; mt++) {
            pmax[mt][0] = fmaxf(pmax[mt][0], __shfl_xor_sync(0xffffffffu, pmax[mt][0], 1));
            pmax[mt][0] = fmaxf(pmax[mt][0], __shfl_xor_sync(0xffffffffu, pmax[mt][0], 2));
            pmax[mt][1] = fmaxf(pmax[mt][1], __shfl_xor_sync(0xffffffffu, pmax[mt][1], 1));
            pmax[mt][1] = fmaxf(pmax[mt][1], __shfl_xor_sync(0xffffffffu, pmax[mt][1], 2));
        }
        if (tg == 0) {
            #pragma unroll
            for (int mt = 0; mt < 2; mt++) {
                const int r = wm * 32 + mt * 16 + g;
                pmxS[wn * 128 + r]     = pmax[mt][0];
                pmxS[wn * 128 + r + 8] = pmax[mt][1];
            }
        }
        barn(pairbar, 64);

        float mnew[2][2], fr[2][2];
        #pragma unroll
        for (int mt = 0; mt < 2; mt++) {
            const int r = wm * 32 + mt * 16 + g;
            float oth0 = pmxS[(1 - wn) * 128 + r];
            float oth1 = pmxS[(1 - wn) * 128 + r + 8];
            float mold0 = m_s[r], mold1 = m_s[r + 8];
            mnew[mt][0] = fmaxf(fmaxf(pmax[mt][0], oth0), mold0);
            mnew[mt][1] = fmaxf(fmaxf(pmax[mt][1], oth1), mold1);
            fr[mt][0] = fast_exp(mold0 - mnew[mt][0]);
            fr[mt][1] = fast_exp(mold1 - mnew[mt][1]);
        }

        float psum[2][2] = {{0.f, 0.f}, {0.f, 0.f}};
        #pragma unroll
        for (int mt = 0; mt < 2; mt++) {
            const int mb = wm * 32 + mt * 16;
            #pragma unroll
            for (int nt = 0; nt < 2; nt++) {
                const int nb = wn * 16 + nt * 8;
                const int c0 = nb + 2 * tg;
                const int r0 = mb + g, r1 = mb + g + 8;
                float p00 = fast_exp(sacc[mt][nt][0] - mnew[mt][0]);
                float p01 = fast_exp(sacc[mt][nt][1] - mnew[mt][0]);
                float p10 = fast_exp(sacc[mt][nt][2] - mnew[mt][1]);
                float p11 = fast_exp(sacc[mt][nt][3] - mnew[mt][1]);
                psum[mt][0] += p00 + p01;
                psum[mt][1] += p10 + p11;
                uint2 w0 = {f2tf32(p00), f2tf32(p01)};
                uint2 w1 = {f2tf32(p10), f2tf32(p11)};
                *(uint2*)&Su[r0 * PS + c0] = w0;
                *(uint2*)&Su[r1 * PS + c0] = w1;
            }
        }
        #pragma unroll
        for (int mt = 0; mt < 2; mt++) {
            psum[mt][0] += __shfl_xor_sync(0xffffffffu, psum[mt][0], 1);
            psum[mt][0] += __shfl_xor_sync(0xffffffffu, psum[mt][0], 2);
            psum[mt][1] += __shfl_xor_sync(0xffffffffu, psum[mt][1], 1);
            psum[mt][1] += __shfl_xor_sync(0xffffffffu, psum[mt][1], 2);
        }
        if (tg == 0) {
            #pragma unroll
            for (int mt = 0; mt < 2; mt++) {
                const int r = wm * 32 + mt * 16 + g;
                psmS[wn * 128 + r]     = psum[mt][0];
                psmS[wn * 128 + r + 8] = psum[mt][1];
            }
        }

        cp_wait<0>();            // V(kl) done
        barn(hbar, 256);         // V ready + P/psums visible; S reads done

        if (wn == 0 && tg == 0) {
            #pragma unroll
            for (int mt = 0; mt < 2; mt++) {
                const int r = wm * 32 + mt * 16 + g;
                l_s[r]     = l_s[r]     * fr[mt][0] + psmS[r]     + psmS[128 + r];
                l_s[r + 8] = l_s[r + 8] * fr[mt][1] + psmS[r + 8] + psmS[128 + r + 8];
                m_s[r]     = mnew[mt][0];
                m_s[r + 8] = mnew[mt][1];
            }
        }

        // prefetch K(kl+1): safe, S reads fenced by the barrier above
        if (kl + 1 < nh) {
            #pragma unroll
            for (int i = 0; i < 4; i++) {
                const int idx = tid_h + i * 256;
                const int r = idx >> 5, sg = (idx & 31) * 4;
                cp16(sm_addr(Ks) + (r * PQ + sg) * 4,
                     kbase + (size_t)(k0 + 32 + r) * NQKV + sg);
            }
            cp_commit();
        }

        // ---- O = O*f + P @ V (128x128), warp tile 32x64, 4 k8-steps ----
        #pragma unroll
        for (int mt = 0; mt < 2; mt++)
            #pragma unroll
            for (int nt = 0; nt < 8; nt++) {
                o[mt][nt][0] *= fr[mt][0];  o[mt][nt][1] *= fr[mt][0];
                o[mt][nt][2] *= fr[mt][1];  o[mt][nt][3] *= fr[mt][1];
            }

        #pragma unroll
        for (int ks = 0; ks < 4; ks++) {
            const int kb = ks * 8;
            uint32_t a[2][4];
            ldsm4(a[0], pA[0] + ks * 32);
            ldsm4(a[1], pA[1] + ks * 32);
            #pragma unroll
            for (int nt = 0; nt < 8; nt++) {
                const int nb = wn * 64 + nt * 8;
                uint32_t b0 = Vs[(kb + tg    )*PV + nb + g];
                uint32_t b1 = Vs[(kb + tg + 4)*PV + nb + g];
                #pragma unroll
                for (int mt = 0; mt < 2; mt++)
                    mma8(o[mt][nt], a[mt][0], a[mt][1], a[mt][2], a[mt][3], b0, b1);
            }
        }
        barn(hbar, 256);         // PV reads done -> V/Su reusable

        if (kl + 1 < nh) {
            #pragma unroll
            for (int i = 0; i < 4; i++) {
                const int idx = tid_h + i * 256;
                const int r = idx >> 5, sg = (idx & 31) * 4;
                cp16(sm_addr(Vs) + (r * PV + sg) * 4,
                     vbase + (size_t)(k0 + 32 + r) * NQKV + sg);
            }
            cp_commit();
        }
    }

    // ---- merge halves ----
    __syncthreads();
    if (half == 1) {
        float* Of = (float*)Qs;   // Q dead; stride PQ floats
        #pragma unroll
        for (int mt = 0; mt < 2; mt++) {
            const int r0 = wm * 32 + mt * 16 + g, r1 = r0 + 8;
            #pragma unroll
            for (int nt = 0; nt < 8; nt++) {
                const int col = wn * 64 + nt * 8 + 2 * tg;
                *(float2*)&Of[r0 * PQ + col] = make_float2(o[mt][nt][0], o[mt][nt][1]);
                *(float2*)&Of[r1 * PQ + col] = make_float2(o[mt][nt][2], o[mt][nt][3]);
            }
        }
    }
    __syncthreads();
    if (half == 0) {
        const float* Of  = (const float*)Qs;
        const float* m1  = (const float*)(smem_u + AQ_U32 + H_U32 + H_M);
        const float* l1  = m1 + 128;
        #pragma unroll
        for (int mt = 0; mt < 2; mt++) {
            const int rA = wm * 32 + mt * 16 + g, rB = rA + 8;
            float mA0 = m_s[rA], mB0 = m1[rA];
            float mA1 = m_s[rB], mB1 = m1[rB];
            float m0 = fmaxf(mA0, mB0), m1v = fmaxf(mA1, mB1);
            float fA0 = fast_exp(mA0 - m0),  fB0 = fast_exp(mB0 - m0);
            float fA1 = fast_exp(mA1 - m1v), fB1 = fast_exp(mB1 - m1v);
            float li0 = 1.f / (l_s[rA] * fA0 + l1[rA] * fB0);
            float li1 = 1.f / (l_s[rB] * fA1 + l1[rB] * fB1);
            #pragma unroll
            for (int nt = 0; nt < 8; nt++) {
                const int col = wn * 64 + nt * 8 + 2 * tg;
                float2 ob0 = *(const float2*)&Of[rA * PQ + col];
                float2 ob1 = *(const float2*)&Of[rB * PQ + col];
                size_t row0 = (size_t)(b * SEQ + q0 + rA) * H + hh * HD + col;
                size_t row1 = (size_t)(b * SEQ + q0 + rB) * H + hh * HD + col;
                float2 r0 = {
                    __uint_as_float(f2tf32((o[mt][nt][0] * fA0 + ob0.x * fB0) * li0)),
                    __uint_as_float(f2tf32((o[mt][nt][1] * fA0 + ob0.y * fB0) * li0))};
                float2 r1 = {
                    __uint_as_float(f2tf32((o[mt][nt][2] * fA1 + ob1.x * fB1) * li1)),
                    __uint_as_float(f2tf32((o[mt][nt][3] * fA1 + ob1.y * fB1) * li1))};
                *(float2*)(out + row0) = r0;
                *(float2*)(out + row1) = r1;
            }
        }
    }
}

// ---------------------------------------------------------------------------

extern "C" void kernel_launch(void* const* d_in, const int* in_sizes, int n_in,
                              void* d_out, int out_size)
{
    (void)in_sizes; (void)n_in; (void)out_size;
    const float* x     = (const float*)d_in[0];
    const float* Wqkv  = (const float*)d_in[1];
    const float* bqkv  = (const float*)d_in[2];
    const float* Wproj = (const float*)d_in[3];
    const float* bproj = (const float*)d_in[4];
    float* out = (float*)d_out;

    float *qkv_p, *attn_p;
    uint32_t *xt, *wqt, *wpt;
    cudaGetSymbolAddress((void**)&qkv_p, g_qkv);
    cudaGetSymbolAddress((void**)&attn_p, g_attn);
    cudaGetSymbolAddress((void**)&xt, g_xt);
    cudaGetSymbolAddress((void**)&wqt, g_wqt);
    cudaGetSymbolAddress((void**)&wpt, g_wpt);

    cudaFuncSetAttribute(mqa_attn_tf32, cudaFuncAttributeMaxDynamicSharedMemorySize,
                         ATTN_SMEM_BYTES);
    cudaFuncSetAttribute(gemm_tf32ca<true>, cudaFuncAttributeMaxDynamicSharedMemorySize,
                         GEMM_SMEM_BYTES);
    cudaFuncSetAttribute(gemm_tf32ca<false>, cudaFuncAttributeMaxDynamicSharedMemorySize,
                         GEMM_SMEM_BYTES);

    // 0) pre-round + pre-transpose
    round_tf32<<<(MROWS * H / 4 + 255) / 256, 256>>>(x, xt, MROWS * H / 4);
    transpose_round<<<dim3(NQKV / 32, H / 32), 256>>>(Wqkv, wqt, H, NQKV);
    transpose_round<<<dim3(H / 32, H / 32), 256>>>(Wproj, wpt, H, H);

    // 1) QKV GEMM (256x128 tiles, 3-stage cp.async; output tf32-rounded)
    gemm_tf32ca<true><<<dim3(NQKV / 128, MROWS / 256), 512, GEMM_SMEM_BYTES>>>(
        xt, wqt, bqkv, qkv_p, H, NQKV);

    // 2) causal MQA flash attention (split-K halves, phase-staggered)
    mqa_attn_tf32<<<dim3(SEQ / 128, NH, BATCH), 512, ATTN_SMEM_BYTES>>>(qkv_p, attn_p);

    // 3) proj GEMM -> d_out (fp32 output, no rounding)
    gemm_tf32ca<false><<<dim3(H / 128, MROWS / 256), 512, GEMM_SMEM_BYTES>>>(
        (const uint32_t*)attn_p, wpt, bproj, out, H, H);
}